// round 1
// baseline (speedup 1.0000x reference)
#include <cuda_runtime.h>
#include <cub/block/block_radix_sort.cuh>

// Problem constants
#define BATCH 8
#define M_    4096   // H*W
#define C_    256    // feature dim
#define NPOOL 256

// 512 MB scratch for the full correlation volume (allowed: __device__ global)
__device__ float g_corr[(size_t)BATCH * M_ * M_];

// ---------------------------------------------------------------------------
// Kernel 1: batched SGEMM  corr[b] = X[b] * X[b]^T / C
// 128x128 tile, 256 threads, 8x8 micro-tile per thread, K-tile = 16.
// ---------------------------------------------------------------------------
__global__ __launch_bounds__(256) void gemm_kernel(const float* __restrict__ X) {
    const int b = blockIdx.z;
    const float* __restrict__ A  = X + (size_t)b * M_ * C_;
    float* __restrict__       Cb = g_corr + (size_t)b * M_ * M_;

    const int i0 = blockIdx.y * 128;
    const int j0 = blockIdx.x * 128;

    __shared__ float As[16][132];   // [k][row], padded for 16B-aligned rows
    __shared__ float Bs[16][132];

    float acc[8][8];
#pragma unroll
    for (int i = 0; i < 8; i++)
#pragma unroll
        for (int j = 0; j < 8; j++) acc[i][j] = 0.0f;

    const int t  = threadIdx.x;
    const int tx = t & 15;   // 0..15  -> N micro-tile
    const int ty = t >> 4;   // 0..15  -> M micro-tile

    for (int k0 = 0; k0 < C_; k0 += 16) {
        // Load 128 rows x 16 k of A (both operands come from the same matrix).
        // 512 float4 per operand; 2 per thread.
#pragma unroll
        for (int j = 0; j < 2; j++) {
            int q  = t * 2 + j;   // 0..511
            int r  = q >> 2;      // row 0..127
            int kq = q & 3;       // which float4 of the 16-wide k slab
            float4 va = *(const float4*)(A + (size_t)(i0 + r) * C_ + k0 + kq * 4);
            As[kq * 4 + 0][r] = va.x;
            As[kq * 4 + 1][r] = va.y;
            As[kq * 4 + 2][r] = va.z;
            As[kq * 4 + 3][r] = va.w;
            float4 vb = *(const float4*)(A + (size_t)(j0 + r) * C_ + k0 + kq * 4);
            Bs[kq * 4 + 0][r] = vb.x;
            Bs[kq * 4 + 1][r] = vb.y;
            Bs[kq * 4 + 2][r] = vb.z;
            Bs[kq * 4 + 3][r] = vb.w;
        }
        __syncthreads();

#pragma unroll
        for (int kk = 0; kk < 16; kk++) {
            float a[8], bb[8];
            *(float4*)&a[0]  = *(const float4*)&As[kk][ty * 8];
            *(float4*)&a[4]  = *(const float4*)&As[kk][ty * 8 + 4];
            *(float4*)&bb[0] = *(const float4*)&Bs[kk][tx * 8];
            *(float4*)&bb[4] = *(const float4*)&Bs[kk][tx * 8 + 4];
#pragma unroll
            for (int i = 0; i < 8; i++)
#pragma unroll
                for (int j = 0; j < 8; j++) acc[i][j] += a[i] * bb[j];
        }
        __syncthreads();
    }

    const float scale = 1.0f / 256.0f;   // exact power of two
#pragma unroll
    for (int i = 0; i < 8; i++) {
        float4 v0, v1;
        v0.x = acc[i][0] * scale; v0.y = acc[i][1] * scale;
        v0.z = acc[i][2] * scale; v0.w = acc[i][3] * scale;
        v1.x = acc[i][4] * scale; v1.y = acc[i][5] * scale;
        v1.z = acc[i][6] * scale; v1.w = acc[i][7] * scale;
        size_t off = (size_t)(i0 + ty * 8 + i) * M_ + j0 + tx * 8;
        *(float4*)(Cb + off)     = v0;
        *(float4*)(Cb + off + 4) = v1;
    }
}

// ---------------------------------------------------------------------------
// Kernel 2: per-row descending sort (cub BlockRadixSort) + percentile gather
// One CTA per (b, pixel) row: 256 threads x 16 items = 4096 keys.
// ---------------------------------------------------------------------------
static constexpr int ST = 256;
static constexpr int IT = 16;

__global__ __launch_bounds__(ST) void sort_kernel(float* __restrict__ out) {
    using Sorter = cub::BlockRadixSort<float, ST, IT>;
    __shared__ union {
        typename Sorter::TempStorage temp;
        float sorted[M_];
    } smem;

    const int row = blockIdx.x;                       // 0 .. BATCH*M_-1
    const float* __restrict__ src = g_corr + (size_t)row * M_;

    float keys[IT];
#pragma unroll
    for (int i = 0; i < IT; i += 4) {
        float4 v = *(const float4*)(src + threadIdx.x * IT + i);
        keys[i + 0] = v.x; keys[i + 1] = v.y;
        keys[i + 2] = v.z; keys[i + 3] = v.w;
    }

    Sorter(smem.temp).SortDescending(keys);
    __syncthreads();   // temp storage -> sorted[] reuse hazard

#pragma unroll
    for (int i = 0; i < IT; i++) smem.sorted[threadIdx.x * IT + i] = keys[i];
    __syncthreads();

    // ranks = round(linspace(1, 4095, 256)), fp32, round-half-even like jnp
    const int p = threadIdx.x;                        // 0..255
    const float step = 4094.0f / 255.0f;
    int r = (int)rintf(fmaf((float)p, step, 1.0f));
    if (r > M_ - 1) r = M_ - 1;
    if (r < 0)      r = 0;

    out[(size_t)row * NPOOL + p] = smem.sorted[r];
}

// ---------------------------------------------------------------------------
// Launch
// ---------------------------------------------------------------------------
extern "C" void kernel_launch(void* const* d_in, const int* in_sizes, int n_in,
                              void* d_out, int out_size) {
    (void)in_sizes; (void)n_in; (void)out_size;
    const float* x = (const float*)d_in[0];
    float* out = (float*)d_out;

    dim3 ggrid(M_ / 128, M_ / 128, BATCH);
    gemm_kernel<<<ggrid, 256>>>(x);

    sort_kernel<<<BATCH * M_, ST>>>(out);
}

// round 4
// speedup vs baseline: 1.3846x; 1.3846x over previous
#include <cuda_runtime.h>
#include <cuda_bf16.h>
#include <cstdint>
#include <cub/block/block_radix_sort.cuh>

// Problem constants
#define BATCH 8
#define M_    4096   // H*W
#define C_    256    // feature dim
#define NPOOL 256

// Scratch (device globals: allocation-free rule)
__device__ float    g_corr[(size_t)BATCH * M_ * M_];            // 512 MB
__device__ uint32_t g_h[(size_t)BATCH * M_ * C_ / 2];           // bf16 hi, 16 MB
__device__ uint32_t g_l[(size_t)BATCH * M_ * C_ / 2];           // bf16 lo, 16 MB

// ---------------------------------------------------------------------------
// Kernel 0: fp32 -> (H, L) bf16 split, plain row-major [b][m][c]
// ---------------------------------------------------------------------------
__global__ __launch_bounds__(256) void convert_kernel(const float* __restrict__ x) {
    const int idx = blockIdx.x * 256 + threadIdx.x;     // one thread per bf16 pair
    float2 v = ((const float2*)x)[idx];

    __nv_bfloat16 h0 = __float2bfloat16(v.x);
    __nv_bfloat16 h1 = __float2bfloat16(v.y);
    __nv_bfloat16 l0 = __float2bfloat16(v.x - __bfloat162float(h0));
    __nv_bfloat16 l1 = __float2bfloat16(v.y - __bfloat162float(h1));

    g_h[idx] = (uint32_t)__bfloat16_as_ushort(h0) | ((uint32_t)__bfloat16_as_ushort(h1) << 16);
    g_l[idx] = (uint32_t)__bfloat16_as_ushort(l0) | ((uint32_t)__bfloat16_as_ushort(l1) << 16);
}

// ---------------------------------------------------------------------------
// mma.sync helpers (sm_80-era PTX; works on compute_103 non-'a' target)
// ---------------------------------------------------------------------------
__device__ __forceinline__ uint32_t smem_u32(const void* p) {
    uint32_t a;
    asm("{ .reg .u64 t; cvta.to.shared.u64 t, %1; cvt.u32.u64 %0, t; }" : "=r"(a) : "l"(p));
    return a;
}
__device__ __forceinline__ void ldsm_x4(uint32_t& r0, uint32_t& r1, uint32_t& r2, uint32_t& r3,
                                        uint32_t addr) {
    asm volatile("ldmatrix.sync.aligned.m8n8.x4.shared.b16 {%0,%1,%2,%3}, [%4];"
                 : "=r"(r0), "=r"(r1), "=r"(r2), "=r"(r3) : "r"(addr));
}
__device__ __forceinline__ void mma_bf16(float* d, const uint32_t* a, const uint32_t* b) {
    asm volatile("mma.sync.aligned.m16n8k16.row.col.f32.bf16.bf16.f32 "
                 "{%0,%1,%2,%3}, {%4,%5,%6,%7}, {%8,%9}, {%0,%1,%2,%3};"
                 : "+f"(d[0]), "+f"(d[1]), "+f"(d[2]), "+f"(d[3])
                 : "r"(a[0]), "r"(a[1]), "r"(a[2]), "r"(a[3]), "r"(b[0]), "r"(b[1]));
}

// XOR-swizzled smem offset: 64B rows of 4x16B chunks, chunk ^= (row>>1)&3.
// 16B-aligned everywhere; ldmatrix phases and STS.128 fills conflict-free.
__device__ __forceinline__ uint32_t swz(uint32_t row, uint32_t chunk) {
    return row * 64u + ((chunk ^ (row >> 1)) & 3u) * 16u;
}

// ---------------------------------------------------------------------------
// Kernel 1: bf16-split GEMM via warp mma.sync.
//   corr[b] = X X^T / C with X = H + L, dropping LL^T (err ~1e-4).
//   128x128 CTA tile, 8 warps of 64x32, K-step 32.
// ---------------------------------------------------------------------------
#define TILE_SM (128 * 64)        // 8192 B per operand tile

__global__ __launch_bounds__(256) void gemm_mma_kernel() {
    __shared__ __align__(16) unsigned char sm[4 * TILE_SM];   // Ah, Al, Bh, Bl

    const int t    = threadIdx.x;
    const int wid  = t >> 5;
    const int lane = t & 31;
    const int b    = blockIdx.z;
    const int ti   = blockIdx.y;
    const int tj   = blockIdx.x;

    const uint32_t sbase = smem_u32(sm);
    const uint32_t OFF_AH = 0, OFF_AL = TILE_SM, OFF_BH = 2 * TILE_SM, OFF_BL = 3 * TILE_SM;

    const unsigned char* gh = (const unsigned char*)g_h;
    const unsigned char* gl = (const unsigned char*)g_l;
    const size_t rowA = (size_t)(b * M_ + ti * 128);   // first A row
    const size_t rowB = (size_t)(b * M_ + tj * 128);   // first B row

    const int mw = (wid & 1) * 64;    // warp M origin in tile
    const int nw = (wid >> 1) * 32;   // warp N origin in tile

    float acc[4][4][4];
#pragma unroll
    for (int i = 0; i < 4; i++)
#pragma unroll
        for (int j = 0; j < 4; j++)
#pragma unroll
            for (int c = 0; c < 4; c++) acc[i][j][c] = 0.0f;

    for (int k0 = 0; k0 < C_; k0 += 32) {
        // ---- fill 4 operand tiles: 128 rows x 32 bf16 (64 B) each ----
#pragma unroll
        for (int j = 0; j < 2; j++) {
            const int q = j * 256 + t;       // 0..511
            const int r = q >> 2;            // row 0..127
            const int c = q & 3;             // 16B chunk
            const size_t gbyteA = (rowA + r) * (C_ * 2) + (size_t)(k0 + c * 8) * 2;
            const size_t gbyteB = (rowB + r) * (C_ * 2) + (size_t)(k0 + c * 8) * 2;
            const uint32_t so = swz((uint32_t)r, (uint32_t)c);
            *(float4*)(sm + OFF_AH + so) = *(const float4*)(gh + gbyteA);
            *(float4*)(sm + OFF_AL + so) = *(const float4*)(gl + gbyteA);
            *(float4*)(sm + OFF_BH + so) = *(const float4*)(gh + gbyteB);
            *(float4*)(sm + OFF_BL + so) = *(const float4*)(gl + gbyteB);
        }
        __syncthreads();

        // ---- 3 split products: HH, HL, LH ----
#pragma unroll
        for (int p = 0; p < 3; p++) {
            const uint32_t sA = sbase + (p == 2 ? OFF_AL : OFF_AH);
            const uint32_t sB = sbase + (p == 1 ? OFF_BL : OFF_BH);
#pragma unroll
            for (int k16 = 0; k16 < 2; k16++) {
                uint32_t a[4][4];
#pragma unroll
                for (int i = 0; i < 4; i++) {
                    const uint32_t arow = (uint32_t)(mw + i * 16 + (lane & 15));
                    const uint32_t achk = (uint32_t)(k16 * 2 + ((lane >> 4) & 1));
                    ldsm_x4(a[i][0], a[i][1], a[i][2], a[i][3], sA + swz(arow, achk));
                }
                uint32_t bf[4][2];
#pragma unroll
                for (int jb = 0; jb < 2; jb++) {
                    const uint32_t brow = (uint32_t)(nw + jb * 16 + (lane & 7) +
                                                     ((lane >> 4) & 1) * 8);
                    const uint32_t bchk = (uint32_t)(k16 * 2 + ((lane >> 3) & 1));
                    uint32_t r0, r1, r2, r3;
                    ldsm_x4(r0, r1, r2, r3, sB + swz(brow, bchk));
                    bf[jb * 2 + 0][0] = r0; bf[jb * 2 + 0][1] = r1;
                    bf[jb * 2 + 1][0] = r2; bf[jb * 2 + 1][1] = r3;
                }
#pragma unroll
                for (int i = 0; i < 4; i++)
#pragma unroll
                    for (int j = 0; j < 4; j++)
                        mma_bf16(acc[i][j], a[i], bf[j]);
            }
        }
        __syncthreads();
    }

    // ---- epilogue: direct stores, scale by 1/C ----
    const float scale = 1.0f / 256.0f;
    const int g4  = lane >> 2;       // 0..7
    const int t4  = lane & 3;        // 0..3
    float* Cb = g_corr + (size_t)b * M_ * M_;
    const int colb = tj * 128 + nw + t4 * 2;
#pragma unroll
    for (int i = 0; i < 4; i++) {
        const int row0 = ti * 128 + mw + i * 16 + g4;
#pragma unroll
        for (int j = 0; j < 4; j++) {
            float2 v0 = make_float2(acc[i][j][0] * scale, acc[i][j][1] * scale);
            float2 v1 = make_float2(acc[i][j][2] * scale, acc[i][j][3] * scale);
            *(float2*)(Cb + (size_t)row0 * M_ + colb + j * 8)       = v0;
            *(float2*)(Cb + (size_t)(row0 + 8) * M_ + colb + j * 8) = v1;
        }
    }
}

// ---------------------------------------------------------------------------
// Kernel 2: per-row descending sort (cub) + percentile gather
// ---------------------------------------------------------------------------
static constexpr int ST = 256;
static constexpr int IT = 16;

__global__ __launch_bounds__(ST) void sort_kernel(float* __restrict__ out) {
    using Sorter = cub::BlockRadixSort<float, ST, IT>;
    __shared__ union {
        typename Sorter::TempStorage temp;
        float sorted[M_];
    } smem;

    const int row = blockIdx.x;
    const float* __restrict__ src = g_corr + (size_t)row * M_;

    float keys[IT];
#pragma unroll
    for (int i = 0; i < IT; i += 4) {
        float4 v = *(const float4*)(src + threadIdx.x * IT + i);
        keys[i + 0] = v.x; keys[i + 1] = v.y;
        keys[i + 2] = v.z; keys[i + 3] = v.w;
    }

    Sorter(smem.temp).SortDescending(keys);
    __syncthreads();

#pragma unroll
    for (int i = 0; i < IT; i++) smem.sorted[threadIdx.x * IT + i] = keys[i];
    __syncthreads();

    const int p = threadIdx.x;
    const float step = 4094.0f / 255.0f;
    int r = (int)rintf(fmaf((float)p, step, 1.0f));
    if (r > M_ - 1) r = M_ - 1;
    if (r < 0)      r = 0;

    out[(size_t)row * NPOOL + p] = smem.sorted[r];
}

// ---------------------------------------------------------------------------
// Launch
// ---------------------------------------------------------------------------
extern "C" void kernel_launch(void* const* d_in, const int* in_sizes, int n_in,
                              void* d_out, int out_size) {
    (void)in_sizes; (void)n_in; (void)out_size;
    const float* x = (const float*)d_in[0];
    float* out = (float*)d_out;

    convert_kernel<<<(BATCH * M_ * C_ / 2) / 256, 256>>>(x);

    dim3 ggrid(M_ / 128, M_ / 128, BATCH);
    gemm_mma_kernel<<<ggrid, 256>>>();

    sort_kernel<<<BATCH * M_, ST>>>(out);
}

// round 5
// speedup vs baseline: 1.9446x; 1.4045x over previous
#include <cuda_runtime.h>
#include <cuda_bf16.h>
#include <cstdint>
#include <cub/block/block_radix_sort.cuh>

// Problem constants
#define BATCH 8
#define M_    4096   // H*W
#define C_    256    // feature dim
#define NPOOL 256
#define NTILE 32                      // M_/128
#define NTRI  (NTILE * (NTILE + 1) / 2)   // 528 lower-triangle tiles

// Scratch (device globals: allocation-free rule)
__device__ float    g_corr[(size_t)BATCH * M_ * M_];            // 512 MB
__device__ uint32_t g_h[(size_t)BATCH * M_ * C_ / 2];           // bf16 hi, 16 MB
__device__ uint32_t g_l[(size_t)BATCH * M_ * C_ / 2];           // bf16 lo, 16 MB

// ---------------------------------------------------------------------------
// Kernel 0: fp32 -> (H, L) bf16 split, plain row-major [b][m][c]
// ---------------------------------------------------------------------------
__global__ __launch_bounds__(256) void convert_kernel(const float* __restrict__ x) {
    const int idx = blockIdx.x * 256 + threadIdx.x;     // one thread per bf16 pair
    float2 v = ((const float2*)x)[idx];

    __nv_bfloat16 h0 = __float2bfloat16(v.x);
    __nv_bfloat16 h1 = __float2bfloat16(v.y);
    __nv_bfloat16 l0 = __float2bfloat16(v.x - __bfloat162float(h0));
    __nv_bfloat16 l1 = __float2bfloat16(v.y - __bfloat162float(h1));

    g_h[idx] = (uint32_t)__bfloat16_as_ushort(h0) | ((uint32_t)__bfloat16_as_ushort(h1) << 16);
    g_l[idx] = (uint32_t)__bfloat16_as_ushort(l0) | ((uint32_t)__bfloat16_as_ushort(l1) << 16);
}

// ---------------------------------------------------------------------------
// mma.sync helpers (sm_80-era PTX; works on compute_103 non-'a' target)
// ---------------------------------------------------------------------------
__device__ __forceinline__ uint32_t smem_u32(const void* p) {
    uint32_t a;
    asm("{ .reg .u64 t; cvta.to.shared.u64 t, %1; cvt.u32.u64 %0, t; }" : "=r"(a) : "l"(p));
    return a;
}
__device__ __forceinline__ void ldsm_x4(uint32_t& r0, uint32_t& r1, uint32_t& r2, uint32_t& r3,
                                        uint32_t addr) {
    asm volatile("ldmatrix.sync.aligned.m8n8.x4.shared.b16 {%0,%1,%2,%3}, [%4];"
                 : "=r"(r0), "=r"(r1), "=r"(r2), "=r"(r3) : "r"(addr));
}
__device__ __forceinline__ void mma_bf16(float* d, const uint32_t* a, const uint32_t* b) {
    asm volatile("mma.sync.aligned.m16n8k16.row.col.f32.bf16.bf16.f32 "
                 "{%0,%1,%2,%3}, {%4,%5,%6,%7}, {%8,%9}, {%0,%1,%2,%3};"
                 : "+f"(d[0]), "+f"(d[1]), "+f"(d[2]), "+f"(d[3])
                 : "r"(a[0]), "r"(a[1]), "r"(a[2]), "r"(a[3]), "r"(b[0]), "r"(b[1]));
}

// XOR-swizzled smem offset: 64B rows of 4x16B chunks, chunk ^= (row>>1)&3.
__device__ __forceinline__ uint32_t swz(uint32_t row, uint32_t chunk) {
    return row * 64u + ((chunk ^ (row >> 1)) & 3u) * 16u;
}

// ---------------------------------------------------------------------------
// Kernel 1: bf16-split GEMM, lower-triangle tiles only (corr is symmetric;
//   computed tile (j,i) is bitwise the transpose of (i,j)).
//   128x128 CTA tile, 8 warps of 64x32, K-step 32, 3 split products.
// ---------------------------------------------------------------------------
#define TILE_SM (128 * 64)        // 8192 B per operand tile
#define STG_P   33                // transpose stage pitch (floats)

union SmemU {
    unsigned char ops[4 * TILE_SM];        // Ah, Al, Bh, Bl (32 KB)
    float stage[128 * STG_P];              // 16.9 KB transpose stage
};

__global__ __launch_bounds__(256) void gemm_mma_kernel() {
    __shared__ __align__(16) SmemU smu;
    unsigned char* sm = smu.ops;

    const int t    = threadIdx.x;
    const int wid  = t >> 5;
    const int lane = t & 31;
    const int b    = blockIdx.z;

    // decode linear triangular index -> (ti >= tj)
    int ti = (int)((sqrtf(8.0f * blockIdx.x + 1.0f) - 1.0f) * 0.5f);
    while ((ti + 1) * (ti + 2) / 2 <= (int)blockIdx.x) ti++;
    while (ti * (ti + 1) / 2 > (int)blockIdx.x) ti--;
    const int tj = blockIdx.x - ti * (ti + 1) / 2;

    const uint32_t sbase = smem_u32(sm);
    const uint32_t OFF_AH = 0, OFF_AL = TILE_SM, OFF_BH = 2 * TILE_SM, OFF_BL = 3 * TILE_SM;

    const unsigned char* gh = (const unsigned char*)g_h;
    const unsigned char* gl = (const unsigned char*)g_l;
    const size_t rowA = (size_t)(b * M_ + ti * 128);
    const size_t rowB = (size_t)(b * M_ + tj * 128);

    const int mw = (wid & 1) * 64;
    const int nw = (wid >> 1) * 32;

    float acc[4][4][4];
#pragma unroll
    for (int i = 0; i < 4; i++)
#pragma unroll
        for (int j = 0; j < 4; j++)
#pragma unroll
            for (int c = 0; c < 4; c++) acc[i][j][c] = 0.0f;

    for (int k0 = 0; k0 < C_; k0 += 32) {
#pragma unroll
        for (int j = 0; j < 2; j++) {
            const int q = j * 256 + t;
            const int r = q >> 2;
            const int c = q & 3;
            const size_t gbyteA = (rowA + r) * (C_ * 2) + (size_t)(k0 + c * 8) * 2;
            const size_t gbyteB = (rowB + r) * (C_ * 2) + (size_t)(k0 + c * 8) * 2;
            const uint32_t so = swz((uint32_t)r, (uint32_t)c);
            *(float4*)(sm + OFF_AH + so) = *(const float4*)(gh + gbyteA);
            *(float4*)(sm + OFF_AL + so) = *(const float4*)(gl + gbyteA);
            *(float4*)(sm + OFF_BH + so) = *(const float4*)(gh + gbyteB);
            *(float4*)(sm + OFF_BL + so) = *(const float4*)(gl + gbyteB);
        }
        __syncthreads();

#pragma unroll
        for (int p = 0; p < 3; p++) {
            const uint32_t sA = sbase + (p == 2 ? OFF_AL : OFF_AH);
            const uint32_t sB = sbase + (p == 1 ? OFF_BL : OFF_BH);
#pragma unroll
            for (int k16 = 0; k16 < 2; k16++) {
                uint32_t a[4][4];
#pragma unroll
                for (int i = 0; i < 4; i++) {
                    const uint32_t arow = (uint32_t)(mw + i * 16 + (lane & 15));
                    const uint32_t achk = (uint32_t)(k16 * 2 + ((lane >> 4) & 1));
                    ldsm_x4(a[i][0], a[i][1], a[i][2], a[i][3], sA + swz(arow, achk));
                }
                uint32_t bf[4][2];
#pragma unroll
                for (int jb = 0; jb < 2; jb++) {
                    const uint32_t brow = (uint32_t)(nw + jb * 16 + (lane & 7) +
                                                     ((lane >> 4) & 1) * 8);
                    const uint32_t bchk = (uint32_t)(k16 * 2 + ((lane >> 3) & 1));
                    uint32_t r0, r1, r2, r3;
                    ldsm_x4(r0, r1, r2, r3, sB + swz(brow, bchk));
                    bf[jb * 2 + 0][0] = r0; bf[jb * 2 + 0][1] = r1;
                    bf[jb * 2 + 1][0] = r2; bf[jb * 2 + 1][1] = r3;
                }
#pragma unroll
                for (int i = 0; i < 4; i++)
#pragma unroll
                    for (int j = 0; j < 4; j++)
                        mma_bf16(acc[i][j], a[i], bf[j]);
            }
        }
        __syncthreads();
    }

    // ---- scale accumulators once ----
    const float scale = 1.0f / 256.0f;
#pragma unroll
    for (int i = 0; i < 4; i++)
#pragma unroll
        for (int j = 0; j < 4; j++)
#pragma unroll
            for (int c = 0; c < 4; c++) acc[i][j][c] *= scale;

    const int g4 = lane >> 2;
    const int t4 = lane & 3;
    float* Cb = g_corr + (size_t)b * M_ * M_;

    // ---- direct store at (ti, tj) ----
    const int colb = tj * 128 + nw + t4 * 2;
#pragma unroll
    for (int i = 0; i < 4; i++) {
        const int row0 = ti * 128 + mw + i * 16 + g4;
#pragma unroll
        for (int j = 0; j < 4; j++) {
            float2 v0 = make_float2(acc[i][j][0], acc[i][j][1]);
            float2 v1 = make_float2(acc[i][j][2], acc[i][j][3]);
            *(float2*)(Cb + (size_t)row0 * M_ + colb + j * 8)       = v0;
            *(float2*)(Cb + (size_t)(row0 + 8) * M_ + colb + j * 8) = v1;
        }
    }

    // ---- transposed store at (tj, ti), off-diagonal only ----
    if (ti != tj) {
        for (int ch = 0; ch < 4; ch++) {       // 32-column chunks of C
            __syncthreads();                   // stage reuse / ops retire
            if ((wid >> 1) == ch) {
                // this warp pair owns cols [32ch, 32ch+32)
#pragma unroll
                for (int i = 0; i < 4; i++) {
                    const int r0 = mw + i * 16 + g4;
#pragma unroll
                    for (int j = 0; j < 4; j++) {
                        const int cl = t4 * 2 + j * 8;    // col within chunk
                        smu.stage[r0 * STG_P + cl]            = acc[i][j][0];
                        smu.stage[r0 * STG_P + cl + 1]        = acc[i][j][1];
                        smu.stage[(r0 + 8) * STG_P + cl]      = acc[i][j][2];
                        smu.stage[(r0 + 8) * STG_P + cl + 1]  = acc[i][j][3];
                    }
                }
            }
            __syncthreads();
            // write 32 transposed rows (= cols of C), each 128 wide, coalesced
#pragma unroll
            for (int s = 0; s < 4; s++) {
                const int cc = wid + s * 8;    // transposed row within chunk
                float* dst = Cb + (size_t)(tj * 128 + ch * 32 + cc) * M_ + ti * 128;
#pragma unroll
                for (int k = 0; k < 4; k++)
                    dst[lane + 32 * k] = smu.stage[(lane + 32 * k) * STG_P + cc];
            }
        }
    }
}

// ---------------------------------------------------------------------------
// Kernel 2: per-row descending sort (cub, 24-bit passes) + percentile gather
// ---------------------------------------------------------------------------
static constexpr int ST = 256;
static constexpr int IT = 16;

__global__ __launch_bounds__(ST) void sort_kernel(float* __restrict__ out) {
    using Sorter = cub::BlockRadixSort<float, ST, IT>;
    __shared__ union {
        typename Sorter::TempStorage temp;
        float sorted[M_];
    } smem;

    const int row = blockIdx.x;
    const float* __restrict__ src = g_corr + (size_t)row * M_;

    float keys[IT];
#pragma unroll
    for (int i = 0; i < IT; i += 4) {
        float4 v = *(const float4*)(src + threadIdx.x * IT + i);
        keys[i + 0] = v.x; keys[i + 1] = v.y;
        keys[i + 2] = v.z; keys[i + 3] = v.w;
    }

    // sort only bits [8,32): 6 radix passes instead of 8; tie error <= 2^-15 rel
    Sorter(smem.temp).SortDescending(keys, 8, 32);
    __syncthreads();

#pragma unroll
    for (int i = 0; i < IT; i++) smem.sorted[threadIdx.x * IT + i] = keys[i];
    __syncthreads();

    const int p = threadIdx.x;
    const float step = 4094.0f / 255.0f;
    int r = (int)rintf(fmaf((float)p, step, 1.0f));
    if (r > M_ - 1) r = M_ - 1;
    if (r < 0)      r = 0;

    out[(size_t)row * NPOOL + p] = smem.sorted[r];
}

// ---------------------------------------------------------------------------
// Launch
// ---------------------------------------------------------------------------
extern "C" void kernel_launch(void* const* d_in, const int* in_sizes, int n_in,
                              void* d_out, int out_size) {
    (void)in_sizes; (void)n_in; (void)out_size;
    const float* x = (const float*)d_in[0];
    float* out = (float*)d_out;

    convert_kernel<<<(BATCH * M_ * C_ / 2) / 256, 256>>>(x);

    dim3 ggrid(NTRI, 1, BATCH);
    gemm_mma_kernel<<<ggrid, 256>>>();

    sort_kernel<<<BATCH * M_, ST>>>(out);
}